// round 13
// baseline (speedup 1.0000x reference)
#include <cuda_runtime.h>
#include <cuda_bf16.h>
#include <math.h>
#include <stdint.h>

#define Bb 2
#define Ss 2048
#define Dd 2048
#define Hh 16
#define HDd 128
#define BSr (Bb*Ss)
#define K3d (3*Dd)
#define KQ3 (3*HDd)                 // 384
#define NT 32
#define NTRI 528
#define OUT_ELEMS (Bb*Ss*Dd)
#define QSCALE 0.08838834764831843f

// ---------------- scratch (device globals; referenced only from device code) ----
__device__ float g_v[Bb*Hh*Ss*HDd];
__device__ float g_ctx[Bb*Ss*Dd];
__device__ float g_lse[Bb*Hh*Ss];
__device__ float g_kpm_add[BSr];
__device__ float g_sc[(size_t)Bb*NTRI*Hh*4096];       // biased scores, lower-tri tiles
__device__ __nv_bfloat16 g_qs[(size_t)Bb*Hh*Ss*KQ3];  // q split [h|h|l], pre-scaled
__device__ __nv_bfloat16 g_ks[(size_t)Bb*Hh*Ss*KQ3];  // k split [h|l|h]
__device__ __nv_bfloat16 g_vt[(size_t)Bb*Hh*HDd*3*Ss];// V^T split [bh][d][h|l|h over s]
__device__ __nv_bfloat16 g_xa[(size_t)BSr*K3d];
__device__ __nv_bfloat16 g_wia[(size_t)3*Dd*K3d];
__device__ __nv_bfloat16 g_woa[(size_t)Dd*K3d];
__device__ __nv_bfloat16 g_ctxa[(size_t)BSr*K3d];

__device__ __forceinline__ void mma16816(float* c, const uint32_t* a, const uint32_t* b) {
    asm volatile("mma.sync.aligned.m16n8k16.row.col.f32.bf16.bf16.f32 "
        "{%0,%1,%2,%3}, {%4,%5,%6,%7}, {%8,%9}, {%0,%1,%2,%3};"
        : "+f"(c[0]), "+f"(c[1]), "+f"(c[2]), "+f"(c[3])
        : "r"(a[0]), "r"(a[1]), "r"(a[2]), "r"(a[3]), "r"(b[0]), "r"(b[1]));
}
__device__ __forceinline__ uint32_t pack_bf2(float x, float y) {
    __nv_bfloat162 p = __floats2bfloat162_rn(x, y);
    return *(uint32_t*)&p;
}
__device__ __forceinline__ uint32_t smem_u32(const void* p) {
    uint32_t a;
    asm("{ .reg .u64 t; cvta.to.shared.u64 t, %1; cvt.u32.u64 %0, t; }" : "=r"(a) : "l"(p));
    return a;
}
__device__ __forceinline__ void cp16(uint32_t saddr, const void* gaddr) {
    asm volatile("cp.async.cg.shared.global [%0], [%1], 16;" :: "r"(saddr), "l"(gaddr));
}
#define CP_COMMIT() asm volatile("cp.async.commit_group;" ::: "memory")
#define CP_WAIT(n)  asm volatile("cp.async.wait_group %0;" :: "n"(n) : "memory")

// ---------------- key_padding_mask normalizer ----------------
__global__ void mask_norm_kernel(const void* kpm, int n)
{
    __shared__ int s_mode;
    __shared__ int c_upper, c_lower, c_fbad;
    const unsigned char* bp = (const unsigned char*)kpm;
    const float* fp = (const float*)kpm;
    int tid = threadIdx.x;
    if (tid == 0) { c_upper = 0; c_lower = 0; c_fbad = 0; }
    __syncthreads();
    for (int i = tid; i < n; i += blockDim.x) {
        unsigned char v = bp[i];
        if (v) { if (i & 3) atomicAdd(&c_upper, 1); else atomicAdd(&c_lower, 1); }
    }
    for (int i = tid; i < n / 4; i += blockDim.x) {
        float v = fp[i];
        if (!(v == 0.0f || v == 1.0f)) atomicAdd(&c_fbad, 1);
    }
    __syncthreads();
    if (tid == 0) {
        if (c_upper == 0 && c_lower == 0) s_mode = 2;
        else if (c_fbad == 0) s_mode = 0;
        else if (c_upper == 0) s_mode = 1;
        else s_mode = 2;
    }
    __syncthreads();
    int mode = s_mode;
    for (int i = tid; i < n; i += blockDim.x) {
        bool keep;
        if (mode == 0)      keep = (fp[i] != 0.0f);
        else if (mode == 1) keep = (((const int*)kpm)[i] != 0);
        else                keep = (bp[i] != 0);
        g_kpm_add[i] = keep ? 0.0f : -1e30f;
    }
}

// ---------------- fp32 -> bf16 hi/lo split ----------------
__global__ void split_kernel(const float* __restrict__ src,
                             int K, long long n4, int pat, int dsel)
{
    long long i = (long long)blockIdx.x * blockDim.x + threadIdx.x;
    if (i >= n4) return;
    if (src == nullptr) src = g_ctx;
    __nv_bfloat16* dst = (dsel == 0) ? g_xa : (dsel == 1) ? g_wia
                       : (dsel == 2) ? g_woa : g_ctxa;
    long long e = i * 4;
    float4 v = *(const float4*)(src + e);
    long long r = e / K; int k = (int)(e - r * K);
    float f[4] = {v.x, v.y, v.z, v.w};
    __nv_bfloat16 h[4], l[4];
    #pragma unroll
    for (int j = 0; j < 4; j++) {
        h[j] = __float2bfloat16(f[j]);
        l[j] = __float2bfloat16(f[j] - __bfloat162float(h[j]));
    }
    __nv_bfloat16* drow = dst + r * (long long)(3 * K);
    uint32_t hp0 = ((uint32_t)__bfloat16_as_ushort(h[1]) << 16) | __bfloat16_as_ushort(h[0]);
    uint32_t hp1 = ((uint32_t)__bfloat16_as_ushort(h[3]) << 16) | __bfloat16_as_ushort(h[2]);
    uint32_t lp0 = ((uint32_t)__bfloat16_as_ushort(l[1]) << 16) | __bfloat16_as_ushort(l[0]);
    uint32_t lp1 = ((uint32_t)__bfloat16_as_ushort(l[3]) << 16) | __bfloat16_as_ushort(l[2]);
    uint2 hp = make_uint2(hp0, hp1), lp = make_uint2(lp0, lp1);
    *(uint2*)(drow + k)         = hp;
    *(uint2*)(drow + K + k)     = pat ? lp : hp;
    *(uint2*)(drow + 2*K + k)   = pat ? hp : lp;
}

// ---------------- bf16 mma.sync NT GEMM: 256x128 tiles, 512 thr, cp.async 2-stage -
#define LDW 36
#define TMg 256
#define TNg 128
#define ASTG (TMg*LDW)                // 9216 words
#define BSTG (TNg*LDW)                // 4608 words
#define STGW (ASTG+BSTG)              // words per stage
#define GM_SMEM (2*STGW*4)            // 110592 bytes

__global__ __launch_bounds__(512)
void gemm_mma_kernel(int absel, const float* __restrict__ bias, float* __restrict__ Cout,
                     int N, int K3, int epi)
{
    extern __shared__ uint32_t gsm[];
    uint32_t* Abuf[2] = { gsm,        gsm + STGW };
    uint32_t* Bbuf[2] = { gsm + ASTG, gsm + STGW + ASTG };
    uint32_t sA[2] = { smem_u32(Abuf[0]), smem_u32(Abuf[1]) };
    uint32_t sB[2] = { smem_u32(Bbuf[0]), smem_u32(Bbuf[1]) };

    const __nv_bfloat16* A2 = (absel == 0) ? g_xa  : g_ctxa;
    const __nv_bfloat16* B2 = (absel == 0) ? g_wia : g_woa;

    const int tid = threadIdx.x;
    const int m0 = blockIdx.y * TMg, n0 = blockIdx.x * TNg;
    const int NCH = K3 / 64;
    const int wstride = K3 / 2;

    const uint32_t* agw = (const uint32_t*)(A2 + (size_t)m0 * K3);
    const uint32_t* bgw = (const uint32_t*)(B2 + (size_t)n0 * K3);

    const int lrow0 = tid >> 3;        // 0..63
    const int lw    = (tid & 7) * 4;
    // 16 warps: 4(m) x 4(n); warp tile 64x32
    const int w = tid >> 5, l = tid & 31;
    const int wm = (w >> 2) * 64, wn = (w & 3) * 32;
    const int g = l >> 2, t = l & 3;

    float acc[4][4][4];
    #pragma unroll
    for (int i = 0; i < 4; i++)
        #pragma unroll
        for (int j = 0; j < 4; j++)
            #pragma unroll
            for (int q = 0; q < 4; q++) acc[i][j][q] = 0.0f;

    #define GISSUE(c, s) do {                                                   \
        const int cw_ = (c) * 32;                                               \
        _Pragma("unroll")                                                       \
        for (int i_ = 0; i_ < 4; i_++) {                                        \
            int row_ = lrow0 + i_ * 64;                                         \
            cp16(sA[s] + (row_ * LDW + lw) * 4,                                 \
                 agw + (size_t)row_ * wstride + cw_ + lw);                      \
        }                                                                       \
        _Pragma("unroll")                                                       \
        for (int i_ = 0; i_ < 2; i_++) {                                        \
            int row_ = lrow0 + i_ * 64;                                         \
            cp16(sB[s] + (row_ * LDW + lw) * 4,                                 \
                 bgw + (size_t)row_ * wstride + cw_ + lw);                      \
        }                                                                       \
        CP_COMMIT();                                                            \
    } while (0)

    GISSUE(0, 0);
    GISSUE(1, 1);

    for (int c = 0; c < NCH; c++) {
        const int s = c & 1;
        CP_WAIT(1);
        __syncthreads();
        const uint32_t* As = Abuf[s];
        const uint32_t* Bs = Bbuf[s];
        #pragma unroll
        for (int kk = 0; kk < 4; kk++) {
            uint32_t af[4][4];
            #pragma unroll
            for (int mt = 0; mt < 4; mt++) {
                int r0 = wm + mt * 16;
                af[mt][0] = As[(r0 + g    ) * LDW + kk*8 + t    ];
                af[mt][1] = As[(r0 + g + 8) * LDW + kk*8 + t    ];
                af[mt][2] = As[(r0 + g    ) * LDW + kk*8 + t + 4];
                af[mt][3] = As[(r0 + g + 8) * LDW + kk*8 + t + 4];
            }
            uint32_t bfr[4][2];
            #pragma unroll
            for (int nt = 0; nt < 4; nt++) {
                int c0n = wn + nt * 8;
                bfr[nt][0] = Bs[(c0n + g) * LDW + kk*8 + t    ];
                bfr[nt][1] = Bs[(c0n + g) * LDW + kk*8 + t + 4];
            }
            #pragma unroll
            for (int mt = 0; mt < 4; mt++)
                #pragma unroll
                for (int nt = 0; nt < 4; nt++)
                    mma16816(acc[mt][nt], af[mt], bfr[nt]);
        }
        __syncthreads();
        if (c + 2 < NCH) GISSUE(c + 2, s);
    }

    if (epi == 0) {
        float* dstbase = Cout + (size_t)m0 * N + n0;
        #pragma unroll
        for (int mt = 0; mt < 4; mt++)
            #pragma unroll
            for (int rr = 0; rr < 2; rr++) {
                int lr = wm + mt * 16 + g + rr * 8;
                float* drow = dstbase + (size_t)lr * N;
                #pragma unroll
                for (int nt = 0; nt < 4; nt++) {
                    int lc = wn + nt * 8 + 2 * t;
                    int gc = n0 + lc;
                    float2 v;
                    v.x = acc[mt][nt][rr*2 + 0] + bias[gc + 0];
                    v.y = acc[mt][nt][rr*2 + 1] + bias[gc + 1];
                    *(float2*)(drow + lc) = v;
                }
            }
    } else {
        int part = n0 >> 11, d2 = n0 & 2047;
        int h = d2 >> 7;
        int bb = m0 >> 11, s0 = m0 & 2047;
        if (part == 2) {
            float* dstbase = g_v + (((size_t)(bb * Hh + h)) * Ss + s0) * HDd;
            #pragma unroll
            for (int mt = 0; mt < 4; mt++)
                #pragma unroll
                for (int rr = 0; rr < 2; rr++) {
                    int lr = wm + mt * 16 + g + rr * 8;
                    float* drow = dstbase + (size_t)lr * HDd;
                    #pragma unroll
                    for (int nt = 0; nt < 4; nt++) {
                        int lc = wn + nt * 8 + 2 * t;
                        int gc = n0 + lc;
                        float2 v;
                        v.x = acc[mt][nt][rr*2 + 0] + bias[gc + 0];
                        v.y = acc[mt][nt][rr*2 + 1] + bias[gc + 1];
                        *(float2*)(drow + lc) = v;
                    }
                }
        } else {
            __nv_bfloat16* basep = (part == 0) ? g_qs : g_ks;
            float scale = (part == 0) ? QSCALE : 1.0f;
            __nv_bfloat16* dstbase = basep + (((size_t)(bb * Hh + h)) * Ss + s0) * (size_t)KQ3;
            #pragma unroll
            for (int mt = 0; mt < 4; mt++)
                #pragma unroll
                for (int rr = 0; rr < 2; rr++) {
                    int lr = wm + mt * 16 + g + rr * 8;
                    uint32_t* drow = (uint32_t*)(dstbase + (size_t)lr * KQ3);
                    #pragma unroll
                    for (int nt = 0; nt < 4; nt++) {
                        int lc = wn + nt * 8 + 2 * t;
                        int gc = n0 + lc;
                        float vx = (acc[mt][nt][rr*2 + 0] + bias[gc + 0]) * scale;
                        float vy = (acc[mt][nt][rr*2 + 1] + bias[gc + 1]) * scale;
                        float hx = __bfloat162float(__float2bfloat16(vx));
                        float hy = __bfloat162float(__float2bfloat16(vy));
                        uint32_t hi2 = pack_bf2(hx, hy);
                        uint32_t lo2 = pack_bf2(vx - hx, vy - hy);
                        int wd = lc >> 1;
                        drow[wd]       = hi2;
                        drow[64 + wd]  = (part == 0) ? hi2 : lo2;
                        drow[128 + wd] = (part == 0) ? lo2 : hi2;
                    }
                }
        }
    }
}

// ---------------- vsplit: g_v -> g_vt (transpose + hi/lo split, once) ----------
#define VS_SMEM (128*132*4)
__global__ __launch_bounds__(256)
void vsplit_kernel()
{
    extern __shared__ float vsm[];   // [128][132]
    const int tid = threadIdx.x;
    const int sch = blockIdx.x;
    const int bh = blockIdx.y;
    const int s0 = sch * 128;

    const float4* src = (const float4*)(g_v + ((size_t)bh * Ss + s0) * HDd);
    for (int idx = tid; idx < 128 * 32; idx += 256) {
        int row = idx >> 5, c4 = idx & 31;
        *(float4*)&vsm[row * 132 + c4 * 4] = src[row * 32 + c4];
    }
    __syncthreads();

    const int d = tid & 127, half = tid >> 7;
    uint32_t* dstb = (uint32_t*)g_vt + ((size_t)(bh * HDd + d) * 3) * (Ss/2) + ((s0 + half * 64) >> 1);
    #pragma unroll
    for (int g8 = 0; g8 < 8; g8++) {
        int sb = half * 64 + g8 * 8;
        float f[8];
        #pragma unroll
        for (int e = 0; e < 8; e++) f[e] = vsm[(sb + e) * 132 + d];
        uint32_t hw[4], lw[4];
        #pragma unroll
        for (int p = 0; p < 4; p++) {
            float a = f[2*p], bq = f[2*p+1];
            float ha = __bfloat162float(__float2bfloat16(a));
            float hb = __bfloat162float(__float2bfloat16(bq));
            hw[p] = pack_bf2(a, bq);
            lw[p] = pack_bf2(a - ha, bq - hb);
        }
        uint4 hv = make_uint4(hw[0], hw[1], hw[2], hw[3]);
        uint4 lv = make_uint4(lw[0], lw[1], lw[2], lw[3]);
        *(uint4*)&dstb[g8 * 4]              = hv;
        *(uint4*)&dstb[(Ss/2) + g8 * 4]     = lv;
        *(uint4*)&dstb[2*(Ss/2) + g8 * 4]   = hv;
    }
}

// ---------------- flash forward: ctx + lse + score spill (R8 version) ----------
#define QKLDW 196
#define PVLDW 100
#define FL_QS   0
#define FL_KS   (FL_QS + 64*QKLDW)
#define FL_VT   (FL_KS + 64*QKLDW)
#define FL_PB   (FL_VT + 128*PVLDW)
#define FL_PS   (FL_PB + 64*PVLDW)
#define FL_RM   (FL_PS + 64*68)
#define FL_RL   (FL_RM + 64)
#define FL_RC   (FL_RL + 64)
#define FL_KA   (FL_RC + 64)
#define FL_WORDS (FL_KA + 64)
#define FLASH_SMEM (FL_WORDS*4)

__global__ __launch_bounds__(256, 1)
void flash_kernel()
{
    extern __shared__ uint32_t smw[];
    uint32_t* Qw  = smw + FL_QS;
    uint32_t* Kw  = smw + FL_KS;
    uint32_t* Vtw = smw + FL_VT;
    uint32_t* Pbw = smw + FL_PB;
    float* Ps   = (float*)(smw + FL_PS);
    float* rowM = (float*)(smw + FL_RM);
    float* rowL = (float*)(smw + FL_RL);
    float* rowC = (float*)(smw + FL_RC);
    float* kadd = (float*)(smw + FL_KA);

    const int tid = threadIdx.x;
    const int bh = blockIdx.y;
    const int b = bh >> 4, h = bh & 15;
    const int qt = (int)gridDim.x - 1 - (int)blockIdx.x;
    const int q0 = qt * 64;
    const float slope = exp2f(-0.5f * (float)(h + 1));

    const int w = tid >> 5, l = tid & 31;
    const int wqk = w >> 1;
    const int wn0 = (w & 1) * 32;
    const int wo0 = (w & 1) * 64;
    const int g = l >> 2, t = l & 3;
    const int r0l = 16 * wqk;
    const int sr = tid >> 2, sq = tid & 3;

    {
        const int r = tid >> 2, u = tid & 3;
        const uint4* src = (const uint4*)(g_qs + ((size_t)bh * Ss + q0 + r) * KQ3);
        #pragma unroll
        for (int i = 0; i < 12; i++)
            *(uint4*)&Qw[r * QKLDW + (u + 4*i) * 4] = src[u + 4*i];
    }
    if (tid < 64) { rowM[tid] = -1e30f; rowL[tid] = 0.0f; }

    float O[8][4];
    #pragma unroll
    for (int i = 0; i < 8; i++)
        #pragma unroll
        for (int q = 0; q < 4; q++) O[i][q] = 0.0f;

    for (int kt = 0; kt <= qt; kt++) {
        const int k0 = kt * 64;
        float* scp = g_sc + (((size_t)b * NTRI + (size_t)(qt*(qt+1)/2 + kt)) * Hh + h) * 4096;
        __syncthreads();
        {
            const int r = tid >> 2, u = tid & 3;
            const uint4* src = (const uint4*)(g_ks + ((size_t)bh * Ss + k0 + r) * KQ3);
            #pragma unroll
            for (int i = 0; i < 12; i++)
                *(uint4*)&Kw[r * QKLDW + (u + 4*i) * 4] = src[u + 4*i];
        }
        {
            const int r2 = tid >> 1, u2 = tid & 1;
            const uint32_t* vtb = (const uint32_t*)g_vt + ((size_t)(bh * HDd + r2) * 3) * (Ss/2) + (k0 >> 1);
            #pragma unroll
            for (int i = 0; i < 12; i++) {
                int wpos = (u2 + 2*i) * 4;
                int seg = wpos >> 5, wseg = wpos & 31;
                *(uint4*)&Vtw[r2 * PVLDW + wpos] = *(const uint4*)(vtb + (size_t)seg * (Ss/2) + wseg);
            }
        }
        if (tid < 64) kadd[tid] = g_kpm_add[b * Ss + k0 + tid];
        __syncthreads();

        float sacc[4][4];
        #pragma unroll
        for (int i = 0; i < 4; i++)
            #pragma unroll
            for (int q = 0; q < 4; q++) sacc[i][q] = 0.0f;
        #pragma unroll 8
        for (int kk = 0; kk < 24; kk++) {
            uint32_t af[4];
            af[0] = Qw[(r0l + g    ) * QKLDW + kk*8 + t    ];
            af[1] = Qw[(r0l + g + 8) * QKLDW + kk*8 + t    ];
            af[2] = Qw[(r0l + g    ) * QKLDW + kk*8 + t + 4];
            af[3] = Qw[(r0l + g + 8) * QKLDW + kk*8 + t + 4];
            #pragma unroll
            for (int nt = 0; nt < 4; nt++) {
                uint32_t bfr[2];
                int c0n = wn0 + nt * 8;
                bfr[0] = Kw[(c0n + g) * QKLDW + kk*8 + t    ];
                bfr[1] = Kw[(c0n + g) * QKLDW + kk*8 + t + 4];
                mma16816(sacc[nt], af, bfr);
            }
        }
        #pragma unroll
        for (int nt = 0; nt < 4; nt++) {
            int colb = wn0 + nt * 8 + 2 * t;
            int kj0 = k0 + colb;
            float ka0 = kadd[colb], ka1 = kadd[colb + 1];
            int qi0 = q0 + r0l + g;
            int qi1 = qi0 + 8;
            float2 s0, s1;
            s0.x = (kj0     > qi0) ? -1e30f : sacc[nt][0] + (float)(kj0     - qi0) * slope + ka0;
            s0.y = (kj0 + 1 > qi0) ? -1e30f : sacc[nt][1] + (float)(kj0 + 1 - qi0) * slope + ka1;
            s1.x = (kj0     > qi1) ? -1e30f : sacc[nt][2] + (float)(kj0     - qi1) * slope + ka0;
            s1.y = (kj0 + 1 > qi1) ? -1e30f : sacc[nt][3] + (float)(kj0 + 1 - qi1) * slope + ka1;
            *(float2*)&Ps[(r0l + g    ) * 68 + colb] = s0;
            *(float2*)&Ps[(r0l + g + 8) * 68 + colb] = s1;
            *(float2*)&scp[(r0l + g    ) * 64 + colb] = s0;
            *(float2*)&scp[(r0l + g + 8) * 64 + colb] = s1;
        }
        __syncthreads();

        {
            float sv[16];
            const float4* pr = (const float4*)(Ps + sr * 68 + sq * 16);
            #pragma unroll
            for (int i = 0; i < 4; i++) {
                float4 v = pr[i];
                sv[4*i+0] = v.x; sv[4*i+1] = v.y; sv[4*i+2] = v.z; sv[4*i+3] = v.w;
            }
            float mt = -1e30f;
            #pragma unroll
            for (int j = 0; j < 16; j++) mt = fmaxf(mt, sv[j]);
            mt = fmaxf(mt, __shfl_xor_sync(0xffffffffu, mt, 1));
            mt = fmaxf(mt, __shfl_xor_sync(0xffffffffu, mt, 2));
            float mold = rowM[sr];
            float mnew = fmaxf(mold, mt);
            float p[16];
            if (mnew < -1e29f) {
                #pragma unroll
                for (int j = 0; j < 16; j++) p[j] = 0.0f;
                if (sq == 0) rowC[sr] = 1.0f;
            } else {
                float corr = __expf(mold - mnew);
                float sum = 0.0f;
                #pragma unroll
                for (int j = 0; j < 16; j++) { p[j] = __expf(sv[j] - mnew); sum += p[j]; }
                sum += __shfl_xor_sync(0xffffffffu, sum, 1);
                sum += __shfl_xor_sync(0xffffffffu, sum, 2);
                if (sq == 0) {
                    rowM[sr] = mnew;
                    rowL[sr] = rowL[sr] * corr + sum;
                    rowC[sr] = corr;
                }
            }
            uint32_t* pw = Pbw + sr * PVLDW + sq * 8;
            #pragma unroll
            for (int j = 0; j < 8; j++) {
                float a = p[2*j], bq = p[2*j+1];
                float ha = __bfloat162float(__float2bfloat16(a));
                float hb = __bfloat162float(__float2bfloat16(bq));
                uint32_t hw = pack_bf2(a, bq);
                uint32_t lw = pack_bf2(a - ha, bq - hb);
                pw[j]      = hw;
                pw[32 + j] = hw;
                pw[64 + j] = lw;
            }
        }
        __syncthreads();

        {
            float cf0 = rowC[r0l + g], cf1 = rowC[r0l + g + 8];
            #pragma unroll
            for (int nt = 0; nt < 8; nt++) {
                O[nt][0] *= cf0; O[nt][1] *= cf0;
                O[nt][2] *= cf1; O[nt][3] *= cf1;
            }
        }
        #pragma unroll 4
        for (int kk = 0; kk < 12; kk++) {
            uint32_t af[4];
            af[0] = Pbw[(r0l + g    ) * PVLDW + kk*8 + t    ];
            af[1] = Pbw[(r0l + g + 8) * PVLDW + kk*8 + t    ];
            af[2] = Pbw[(r0l + g    ) * PVLDW + kk*8 + t + 4];
            af[3] = Pbw[(r0l + g + 8) * PVLDW + kk*8 + t + 4];
            #pragma unroll
            for (int nt = 0; nt < 8; nt++) {
                uint32_t bfr[2];
                int c0n = wo0 + nt * 8;
                bfr[0] = Vtw[(c0n + g) * PVLDW + kk*8 + t    ];
                bfr[1] = Vtw[(c0n + g) * PVLDW + kk*8 + t + 4];
                mma16816(O[nt], af, bfr);
            }
        }
    }

    __syncthreads();
    if (tid < 64) {
        float lsum = rowL[tid];
        rowC[tid] = 1.0f / lsum;
        g_lse[(size_t)bh * Ss + q0 + tid] = rowM[tid] + logf(lsum);
    }
    __syncthreads();
    {
        float invl0 = rowC[r0l + g], invl1 = rowC[r0l + g + 8];
        float* d0 = g_ctx + ((size_t)(b * Ss + q0 + r0l + g    )) * Dd + h * HDd;
        float* d1 = g_ctx + ((size_t)(b * Ss + q0 + r0l + g + 8)) * Dd + h * HDd;
        #pragma unroll
        for (int nt = 0; nt < 8; nt++) {
            int col = wo0 + nt * 8 + 2 * t;
            *(float2*)(d0 + col) = make_float2(O[nt][0] * invl0, O[nt][1] * invl0);
            *(float2*)(d1 + col) = make_float2(O[nt][2] * invl1, O[nt][3] * invl1);
        }
    }
}

// ---------------- avg_attn: stream spilled scores ----------------
__global__ __launch_bounds__(256)
void avg_kernel(float* __restrict__ avg)
{
    const int tid = threadIdx.x;
    const int b = blockIdx.z, qt = blockIdx.y, kt = blockIdx.x;
    const int q0 = qt * 64, k0 = kt * 64;
    const int r = tid >> 2, c0 = (tid & 3) * 16;
    float* drow = avg + ((size_t)(b * Ss + q0 + r)) * Ss + k0 + c0;

    if (kt > qt) {
        float4 z = make_float4(0.f, 0.f, 0.f, 0.f);
        #pragma unroll
        for (int i = 0; i < 4; i++) ((float4*)drow)[i] = z;
        return;
    }

    size_t tbase = ((size_t)b * NTRI + (size_t)(qt*(qt+1)/2 + kt)) * Hh * 4096;
    float acc[16];
    #pragma unroll
    for (int j = 0; j < 16; j++) acc[j] = 0.0f;

    for (int h = 0; h < Hh; h++) {
        float lse = g_lse[((size_t)(b * Hh + h)) * Ss + q0 + r];
        const float4* sp = (const float4*)(g_sc + tbase + (size_t)h * 4096 + r * 64 + c0);
        #pragma unroll
        for (int i = 0; i < 4; i++) {
            float4 s4 = sp[i];
            acc[4*i+0] += __expf(s4.x - lse);
            acc[4*i+1] += __expf(s4.y - lse);
            acc[4*i+2] += __expf(s4.z - lse);
            acc[4*i+3] += __expf(s4.w - lse);
        }
    }
    #pragma unroll
    for (int i = 0; i < 4; i++) {
        float4 v = make_float4(acc[4*i+0]*0.0625f, acc[4*i+1]*0.0625f,
                               acc[4*i+2]*0.0625f, acc[4*i+3]*0.0625f);
        ((float4*)drow)[i] = v;
    }
}

// ---------------- launch ----------------
extern "C" void kernel_launch(void* const* d_in, const int* in_sizes, int n_in,
                              void* d_out, int out_size)
{
    const float* x    = (const float*)d_in[0];
    const void*  kpm  = d_in[1];
    const float* inw  = (const float*)d_in[3];
    const float* inb  = (const float*)d_in[4];
    const float* outw = (const float*)d_in[5];
    const float* outb = (const float*)d_in[6];

    float* out = (float*)d_out;
    float* avg = out + OUT_ELEMS;

    cudaFuncSetAttribute(gemm_mma_kernel, cudaFuncAttributeMaxDynamicSharedMemorySize, GM_SMEM);
    cudaFuncSetAttribute(flash_kernel, cudaFuncAttributeMaxDynamicSharedMemorySize, FLASH_SMEM);
    cudaFuncSetAttribute(vsplit_kernel, cudaFuncAttributeMaxDynamicSharedMemorySize, VS_SMEM);

    mask_norm_kernel<<<1, 256>>>(kpm, BSr);

    {
        long long n4;
        n4 = (long long)BSr * Dd / 4;
        split_kernel<<<(unsigned)((n4 + 255) / 256), 256>>>(x, Dd, n4, 0, 0);
        n4 = (long long)3 * Dd * Dd / 4;
        split_kernel<<<(unsigned)((n4 + 255) / 256), 256>>>(inw, Dd, n4, 1, 1);
        n4 = (long long)Dd * Dd / 4;
        split_kernel<<<(unsigned)((n4 + 255) / 256), 256>>>(outw, Dd, n4, 1, 2);
    }

    // QKV projection: 256x128 tiles
    gemm_mma_kernel<<<dim3(3*Dd/128, BSr/256), 512, GM_SMEM>>>(0, inb, nullptr, 3*Dd, K3d, 1);

    // one-shot V transpose+split
    vsplit_kernel<<<dim3(Ss/128, Bb*Hh), 256, VS_SMEM>>>();

    // flash attention (spills scores, writes g_ctx fp32)
    flash_kernel<<<dim3(Ss/64, Bb*Hh), 256, FLASH_SMEM>>>();

    // avg_attn: stream scores
    avg_kernel<<<dim3(NT, NT, Bb), 256>>>(avg);

    // ctx split + output projection: 256x128 tiles
    {
        long long n4 = (long long)BSr * Dd / 4;
        split_kernel<<<(unsigned)((n4 + 255) / 256), 256>>>(nullptr, Dd, n4, 0, 3);
    }
    gemm_mma_kernel<<<dim3(Dd/128, BSr/256), 512, GM_SMEM>>>(1, outb, out, Dd, K3d, 0);
}

// round 14
// speedup vs baseline: 1.2525x; 1.2525x over previous
#include <cuda_runtime.h>
#include <cuda_bf16.h>
#include <math.h>
#include <stdint.h>

#define Bb 2
#define Ss 2048
#define Dd 2048
#define Hh 16
#define HDd 128
#define BSr (Bb*Ss)
#define K3d (3*Dd)
#define KQ3 (3*HDd)                 // 384
#define NT 32
#define NTRI 528
#define OUT_ELEMS (Bb*Ss*Dd)
#define QSCALE 0.08838834764831843f

// ---------------- scratch (device globals; referenced only from device code) ----
__device__ float g_v[Bb*Hh*Ss*HDd];
__device__ float g_ctx[Bb*Ss*Dd];
__device__ float g_lse[Bb*Hh*Ss];
__device__ float g_kpm_add[BSr];
__device__ float g_sc[(size_t)Bb*NTRI*Hh*4096];       // biased scores, lower-tri tiles
__device__ __nv_bfloat16 g_qs[(size_t)Bb*Hh*Ss*KQ3];  // q split [h|h|l], pre-scaled
__device__ __nv_bfloat16 g_ks[(size_t)Bb*Hh*Ss*KQ3];  // k split [h|l|h]
__device__ __nv_bfloat16 g_vt[(size_t)Bb*Hh*HDd*3*Ss];// V^T split [bh][d][h|l|h over s]
__device__ __nv_bfloat16 g_xa[(size_t)BSr*K3d];
__device__ __nv_bfloat16 g_wia[(size_t)3*Dd*K3d];
__device__ __nv_bfloat16 g_woa[(size_t)Dd*K3d];
__device__ __nv_bfloat16 g_ctxa[(size_t)BSr*K3d];

__device__ __forceinline__ void mma16816(float* c, const uint32_t* a, const uint32_t* b) {
    asm volatile("mma.sync.aligned.m16n8k16.row.col.f32.bf16.bf16.f32 "
        "{%0,%1,%2,%3}, {%4,%5,%6,%7}, {%8,%9}, {%0,%1,%2,%3};"
        : "+f"(c[0]), "+f"(c[1]), "+f"(c[2]), "+f"(c[3])
        : "r"(a[0]), "r"(a[1]), "r"(a[2]), "r"(a[3]), "r"(b[0]), "r"(b[1]));
}
__device__ __forceinline__ void ldsm4(uint32_t* r, uint32_t saddr) {
    asm volatile("ldmatrix.sync.aligned.m8n8.x4.shared.b16 {%0,%1,%2,%3}, [%4];"
        : "=r"(r[0]), "=r"(r[1]), "=r"(r[2]), "=r"(r[3]) : "r"(saddr));
}
__device__ __forceinline__ uint32_t pack_bf2(float x, float y) {
    __nv_bfloat162 p = __floats2bfloat162_rn(x, y);
    return *(uint32_t*)&p;
}
__device__ __forceinline__ uint32_t smem_u32(const void* p) {
    uint32_t a;
    asm("{ .reg .u64 t; cvta.to.shared.u64 t, %1; cvt.u32.u64 %0, t; }" : "=r"(a) : "l"(p));
    return a;
}

// ---------------- key_padding_mask normalizer ----------------
__global__ void mask_norm_kernel(const void* kpm, int n)
{
    __shared__ int s_mode;
    __shared__ int c_upper, c_lower, c_fbad;
    const unsigned char* bp = (const unsigned char*)kpm;
    const float* fp = (const float*)kpm;
    int tid = threadIdx.x;
    if (tid == 0) { c_upper = 0; c_lower = 0; c_fbad = 0; }
    __syncthreads();
    for (int i = tid; i < n; i += blockDim.x) {
        unsigned char v = bp[i];
        if (v) { if (i & 3) atomicAdd(&c_upper, 1); else atomicAdd(&c_lower, 1); }
    }
    for (int i = tid; i < n / 4; i += blockDim.x) {
        float v = fp[i];
        if (!(v == 0.0f || v == 1.0f)) atomicAdd(&c_fbad, 1);
    }
    __syncthreads();
    if (tid == 0) {
        if (c_upper == 0 && c_lower == 0) s_mode = 2;
        else if (c_fbad == 0) s_mode = 0;
        else if (c_upper == 0) s_mode = 1;
        else s_mode = 2;
    }
    __syncthreads();
    int mode = s_mode;
    for (int i = tid; i < n; i += blockDim.x) {
        bool keep;
        if (mode == 0)      keep = (fp[i] != 0.0f);
        else if (mode == 1) keep = (((const int*)kpm)[i] != 0);
        else                keep = (bp[i] != 0);
        g_kpm_add[i] = keep ? 0.0f : -1e30f;
    }
}

// ---------------- fp32 -> bf16 hi/lo split ----------------
__global__ void split_kernel(const float* __restrict__ src,
                             int K, long long n4, int pat, int dsel)
{
    long long i = (long long)blockIdx.x * blockDim.x + threadIdx.x;
    if (i >= n4) return;
    if (src == nullptr) src = g_ctx;
    __nv_bfloat16* dst = (dsel == 0) ? g_xa : (dsel == 1) ? g_wia
                       : (dsel == 2) ? g_woa : g_ctxa;
    long long e = i * 4;
    float4 v = *(const float4*)(src + e);
    long long r = e / K; int k = (int)(e - r * K);
    float f[4] = {v.x, v.y, v.z, v.w};
    __nv_bfloat16 h[4], l[4];
    #pragma unroll
    for (int j = 0; j < 4; j++) {
        h[j] = __float2bfloat16(f[j]);
        l[j] = __float2bfloat16(f[j] - __bfloat162float(h[j]));
    }
    __nv_bfloat16* drow = dst + r * (long long)(3 * K);
    uint32_t hp0 = ((uint32_t)__bfloat16_as_ushort(h[1]) << 16) | __bfloat16_as_ushort(h[0]);
    uint32_t hp1 = ((uint32_t)__bfloat16_as_ushort(h[3]) << 16) | __bfloat16_as_ushort(h[2]);
    uint32_t lp0 = ((uint32_t)__bfloat16_as_ushort(l[1]) << 16) | __bfloat16_as_ushort(l[0]);
    uint32_t lp1 = ((uint32_t)__bfloat16_as_ushort(l[3]) << 16) | __bfloat16_as_ushort(l[2]);
    uint2 hp = make_uint2(hp0, hp1), lp = make_uint2(lp0, lp1);
    *(uint2*)(drow + k)         = hp;
    *(uint2*)(drow + K + k)     = pat ? lp : hp;
    *(uint2*)(drow + 2*K + k)   = pat ? hp : lp;
}

// ---------------- bf16 mma.sync NT GEMM (R8 register-staged + ldmatrix) ----------
#define LDW 36

__global__ __launch_bounds__(256)
void gemm_mma_kernel(int absel, const float* __restrict__ bias, float* __restrict__ Cout,
                     int N, int K3, int epi)
{
    __shared__ uint32_t As[128*LDW];
    __shared__ uint32_t Bs[128*LDW];

    const __nv_bfloat16* A2 = (absel == 0) ? g_xa  : g_ctxa;
    const __nv_bfloat16* B2 = (absel == 0) ? g_wia : g_woa;

    const int tid = threadIdx.x;
    const int m0 = blockIdx.y * 128, n0 = blockIdx.x * 128;
    const int NCH = K3 / 64;
    const int wstride = K3 / 2;

    const uint32_t* agw = (const uint32_t*)(A2 + (size_t)m0 * K3);
    const uint32_t* bgw = (const uint32_t*)(B2 + (size_t)n0 * K3);

    const int lrow0 = tid >> 3;
    const int lw    = (tid & 7) * 4;
    const int w = tid >> 5, l = tid & 31;
    const int wm = (w >> 2) * 64, wn = (w & 3) * 32;
    const int g = l >> 2, t = l & 3;

    // ldmatrix lane addresses (bytes)
    const uint32_t aAddr = smem_u32(As) + ((((wm + (l & 15)) * LDW) + ((l >> 4) << 2)) << 2);
    const uint32_t bAddr = smem_u32(Bs) + ((((wn + ((l >> 4) << 3) + (l & 7)) * LDW) + (((l >> 3) & 1) << 2)) << 2);

    float acc[4][4][4];
    #pragma unroll
    for (int i = 0; i < 4; i++)
        #pragma unroll
        for (int j = 0; j < 4; j++)
            #pragma unroll
            for (int q = 0; q < 4; q++) acc[i][j][q] = 0.0f;

    uint4 ra[4], rb[4];
    #pragma unroll
    for (int i = 0; i < 4; i++) {
        int row = lrow0 + i * 32;
        ra[i] = *(const uint4*)&agw[(size_t)row * wstride + lw];
        rb[i] = *(const uint4*)&bgw[(size_t)row * wstride + lw];
    }

    for (int c = 0; c < NCH; c++) {
        #pragma unroll
        for (int i = 0; i < 4; i++) {
            int row = lrow0 + i * 32;
            *(uint4*)&As[row * LDW + lw] = ra[i];
            *(uint4*)&Bs[row * LDW + lw] = rb[i];
        }
        __syncthreads();
        if (c + 1 < NCH) {
            const int cw = (c + 1) * 32;
            #pragma unroll
            for (int i = 0; i < 4; i++) {
                int row = lrow0 + i * 32;
                ra[i] = *(const uint4*)&agw[(size_t)row * wstride + cw + lw];
                rb[i] = *(const uint4*)&bgw[(size_t)row * wstride + cw + lw];
            }
        }
        #pragma unroll
        for (int kk = 0; kk < 4; kk++) {
            uint32_t af[4][4];
            #pragma unroll
            for (int mt = 0; mt < 4; mt++)
                ldsm4(af[mt], aAddr + mt * (16 * LDW * 4) + kk * 32);
            uint32_t b01[4], b23[4];
            ldsm4(b01, bAddr + kk * 32);
            ldsm4(b23, bAddr + 16 * LDW * 4 + kk * 32);
            #pragma unroll
            for (int mt = 0; mt < 4; mt++) {
                mma16816(acc[mt][0], af[mt], &b01[0]);
                mma16816(acc[mt][1], af[mt], &b01[2]);
                mma16816(acc[mt][2], af[mt], &b23[0]);
                mma16816(acc[mt][3], af[mt], &b23[2]);
            }
        }
        __syncthreads();
    }

    if (epi == 0) {
        float* dstbase = Cout + (size_t)m0 * N + n0;
        #pragma unroll
        for (int mt = 0; mt < 4; mt++)
            #pragma unroll
            for (int rr = 0; rr < 2; rr++) {
                int lr = wm + mt * 16 + g + rr * 8;
                float* drow = dstbase + (size_t)lr * N;
                #pragma unroll
                for (int nt = 0; nt < 4; nt++) {
                    int lc = wn + nt * 8 + 2 * t;
                    int gc = n0 + lc;
                    float2 v;
                    v.x = acc[mt][nt][rr*2 + 0] + bias[gc + 0];
                    v.y = acc[mt][nt][rr*2 + 1] + bias[gc + 1];
                    *(float2*)(drow + lc) = v;
                }
            }
    } else {
        int part = n0 >> 11, d2 = n0 & 2047;
        int h = d2 >> 7;
        int bb = m0 >> 11, s0 = m0 & 2047;
        if (part == 2) {
            float* dstbase = g_v + (((size_t)(bb * Hh + h)) * Ss + s0) * HDd;
            #pragma unroll
            for (int mt = 0; mt < 4; mt++)
                #pragma unroll
                for (int rr = 0; rr < 2; rr++) {
                    int lr = wm + mt * 16 + g + rr * 8;
                    float* drow = dstbase + (size_t)lr * HDd;
                    #pragma unroll
                    for (int nt = 0; nt < 4; nt++) {
                        int lc = wn + nt * 8 + 2 * t;
                        int gc = n0 + lc;
                        float2 v;
                        v.x = acc[mt][nt][rr*2 + 0] + bias[gc + 0];
                        v.y = acc[mt][nt][rr*2 + 1] + bias[gc + 1];
                        *(float2*)(drow + lc) = v;
                    }
                }
        } else {
            __nv_bfloat16* basep = (part == 0) ? g_qs : g_ks;
            float scale = (part == 0) ? QSCALE : 1.0f;
            __nv_bfloat16* dstbase = basep + (((size_t)(bb * Hh + h)) * Ss + s0) * (size_t)KQ3;
            #pragma unroll
            for (int mt = 0; mt < 4; mt++)
                #pragma unroll
                for (int rr = 0; rr < 2; rr++) {
                    int lr = wm + mt * 16 + g + rr * 8;
                    uint32_t* drow = (uint32_t*)(dstbase + (size_t)lr * KQ3);
                    #pragma unroll
                    for (int nt = 0; nt < 4; nt++) {
                        int lc = wn + nt * 8 + 2 * t;
                        int gc = n0 + lc;
                        float vx = (acc[mt][nt][rr*2 + 0] + bias[gc + 0]) * scale;
                        float vy = (acc[mt][nt][rr*2 + 1] + bias[gc + 1]) * scale;
                        float hx = __bfloat162float(__float2bfloat16(vx));
                        float hy = __bfloat162float(__float2bfloat16(vy));
                        uint32_t hi2 = pack_bf2(hx, hy);
                        uint32_t lo2 = pack_bf2(vx - hx, vy - hy);
                        int wd = lc >> 1;
                        drow[wd]       = hi2;
                        drow[64 + wd]  = (part == 0) ? hi2 : lo2;
                        drow[128 + wd] = (part == 0) ? lo2 : hi2;
                    }
                }
        }
    }
}

// ---------------- vsplit: g_v -> g_vt (transpose + hi/lo split, once) ----------
#define VS_SMEM (128*132*4)
__global__ __launch_bounds__(256)
void vsplit_kernel()
{
    extern __shared__ float vsm[];   // [128][132]
    const int tid = threadIdx.x;
    const int sch = blockIdx.x;
    const int bh = blockIdx.y;
    const int s0 = sch * 128;

    const float4* src = (const float4*)(g_v + ((size_t)bh * Ss + s0) * HDd);
    for (int idx = tid; idx < 128 * 32; idx += 256) {
        int row = idx >> 5, c4 = idx & 31;
        *(float4*)&vsm[row * 132 + c4 * 4] = src[row * 32 + c4];
    }
    __syncthreads();

    const int d = tid & 127, half = tid >> 7;
    uint32_t* dstb = (uint32_t*)g_vt + ((size_t)(bh * HDd + d) * 3) * (Ss/2) + ((s0 + half * 64) >> 1);
    #pragma unroll
    for (int g8 = 0; g8 < 8; g8++) {
        int sb = half * 64 + g8 * 8;
        float f[8];
        #pragma unroll
        for (int e = 0; e < 8; e++) f[e] = vsm[(sb + e) * 132 + d];
        uint32_t hw[4], lw[4];
        #pragma unroll
        for (int p = 0; p < 4; p++) {
            float a = f[2*p], bq = f[2*p+1];
            float ha = __bfloat162float(__float2bfloat16(a));
            float hb = __bfloat162float(__float2bfloat16(bq));
            hw[p] = pack_bf2(a, bq);
            lw[p] = pack_bf2(a - ha, bq - hb);
        }
        uint4 hv = make_uint4(hw[0], hw[1], hw[2], hw[3]);
        uint4 lv = make_uint4(lw[0], lw[1], lw[2], lw[3]);
        *(uint4*)&dstb[g8 * 4]              = hv;
        *(uint4*)&dstb[(Ss/2) + g8 * 4]     = lv;
        *(uint4*)&dstb[2*(Ss/2) + g8 * 4]   = hv;
    }
}

// ---------------- flash forward: ctx + lse + score spill (+ldmatrix) ------------
#define QKLDW 196
#define PVLDW 100
#define FL_QS   0
#define FL_KS   (FL_QS + 64*QKLDW)
#define FL_VT   (FL_KS + 64*QKLDW)
#define FL_PB   (FL_VT + 128*PVLDW)
#define FL_PS   (FL_PB + 64*PVLDW)
#define FL_RM   (FL_PS + 64*68)
#define FL_RL   (FL_RM + 64)
#define FL_RC   (FL_RL + 64)
#define FL_KA   (FL_RC + 64)
#define FL_WORDS (FL_KA + 64)
#define FLASH_SMEM (FL_WORDS*4)

__global__ __launch_bounds__(256, 1)
void flash_kernel()
{
    extern __shared__ uint32_t smw[];
    uint32_t* Qw  = smw + FL_QS;
    uint32_t* Kw  = smw + FL_KS;
    uint32_t* Vtw = smw + FL_VT;
    uint32_t* Pbw = smw + FL_PB;
    float* Ps   = (float*)(smw + FL_PS);
    float* rowM = (float*)(smw + FL_RM);
    float* rowL = (float*)(smw + FL_RL);
    float* rowC = (float*)(smw + FL_RC);
    float* kadd = (float*)(smw + FL_KA);

    const int tid = threadIdx.x;
    const int bh = blockIdx.y;
    const int b = bh >> 4, h = bh & 15;
    const int qt = (int)gridDim.x - 1 - (int)blockIdx.x;
    const int q0 = qt * 64;
    const float slope = exp2f(-0.5f * (float)(h + 1));

    const int w = tid >> 5, l = tid & 31;
    const int wqk = w >> 1;
    const int wn0 = (w & 1) * 32;
    const int wo0 = (w & 1) * 64;
    const int g = l >> 2, t = l & 3;
    const int r0l = 16 * wqk;
    const int sr = tid >> 2, sq = tid & 3;

    // ldmatrix lane addresses (bytes)
    const uint32_t aQaddr = smem_u32(Qw)  + ((((r0l + (l & 15)) * QKLDW) + ((l >> 4) << 2)) << 2);
    const uint32_t bKaddr = smem_u32(Kw)  + ((((wn0 + ((l >> 4) << 3) + (l & 7)) * QKLDW) + (((l >> 3) & 1) << 2)) << 2);
    const uint32_t aPaddr = smem_u32(Pbw) + ((((r0l + (l & 15)) * PVLDW) + ((l >> 4) << 2)) << 2);
    const uint32_t bVaddr = smem_u32(Vtw) + ((((wo0 + ((l >> 4) << 3) + (l & 7)) * PVLDW) + (((l >> 3) & 1) << 2)) << 2);

    {
        const int r = tid >> 2, u = tid & 3;
        const uint4* src = (const uint4*)(g_qs + ((size_t)bh * Ss + q0 + r) * KQ3);
        #pragma unroll
        for (int i = 0; i < 12; i++)
            *(uint4*)&Qw[r * QKLDW + (u + 4*i) * 4] = src[u + 4*i];
    }
    if (tid < 64) { rowM[tid] = -1e30f; rowL[tid] = 0.0f; }

    float O[8][4];
    #pragma unroll
    for (int i = 0; i < 8; i++)
        #pragma unroll
        for (int q = 0; q < 4; q++) O[i][q] = 0.0f;

    for (int kt = 0; kt <= qt; kt++) {
        const int k0 = kt * 64;
        float* scp = g_sc + (((size_t)b * NTRI + (size_t)(qt*(qt+1)/2 + kt)) * Hh + h) * 4096;
        __syncthreads();
        {
            const int r = tid >> 2, u = tid & 3;
            const uint4* src = (const uint4*)(g_ks + ((size_t)bh * Ss + k0 + r) * KQ3);
            #pragma unroll
            for (int i = 0; i < 12; i++)
                *(uint4*)&Kw[r * QKLDW + (u + 4*i) * 4] = src[u + 4*i];
        }
        {
            const int r2 = tid >> 1, u2 = tid & 1;
            const uint32_t* vtb = (const uint32_t*)g_vt + ((size_t)(bh * HDd + r2) * 3) * (Ss/2) + (k0 >> 1);
            #pragma unroll
            for (int i = 0; i < 12; i++) {
                int wpos = (u2 + 2*i) * 4;
                int seg = wpos >> 5, wseg = wpos & 31;
                *(uint4*)&Vtw[r2 * PVLDW + wpos] = *(const uint4*)(vtb + (size_t)seg * (Ss/2) + wseg);
            }
        }
        if (tid < 64) kadd[tid] = g_kpm_add[b * Ss + k0 + tid];
        __syncthreads();

        // ---- QK^T via mma over K'=384 (ldmatrix) ----
        float sacc[4][4];
        #pragma unroll
        for (int i = 0; i < 4; i++)
            #pragma unroll
            for (int q = 0; q < 4; q++) sacc[i][q] = 0.0f;
        #pragma unroll 8
        for (int kk = 0; kk < 24; kk++) {
            uint32_t af[4], b01[4], b23[4];
            ldsm4(af, aQaddr + kk * 32);
            ldsm4(b01, bKaddr + kk * 32);
            ldsm4(b23, bKaddr + (16 * QKLDW << 2) + kk * 32);
            mma16816(sacc[0], af, &b01[0]);
            mma16816(sacc[1], af, &b01[2]);
            mma16816(sacc[2], af, &b23[0]);
            mma16816(sacc[3], af, &b23[2]);
        }
        #pragma unroll
        for (int nt = 0; nt < 4; nt++) {
            int colb = wn0 + nt * 8 + 2 * t;
            int kj0 = k0 + colb;
            float ka0 = kadd[colb], ka1 = kadd[colb + 1];
            int qi0 = q0 + r0l + g;
            int qi1 = qi0 + 8;
            float2 s0, s1;
            s0.x = (kj0     > qi0) ? -1e30f : sacc[nt][0] + (float)(kj0     - qi0) * slope + ka0;
            s0.y = (kj0 + 1 > qi0) ? -1e30f : sacc[nt][1] + (float)(kj0 + 1 - qi0) * slope + ka1;
            s1.x = (kj0     > qi1) ? -1e30f : sacc[nt][2] + (float)(kj0     - qi1) * slope + ka0;
            s1.y = (kj0 + 1 > qi1) ? -1e30f : sacc[nt][3] + (float)(kj0 + 1 - qi1) * slope + ka1;
            *(float2*)&Ps[(r0l + g    ) * 68 + colb] = s0;
            *(float2*)&Ps[(r0l + g + 8) * 68 + colb] = s1;
            *(float2*)&scp[(r0l + g    ) * 64 + colb] = s0;
            *(float2*)&scp[(r0l + g + 8) * 64 + colb] = s1;
        }
        __syncthreads();

        // ---- parallel online softmax (4 threads/row) + fused P split ----
        {
            float sv[16];
            const float4* pr = (const float4*)(Ps + sr * 68 + sq * 16);
            #pragma unroll
            for (int i = 0; i < 4; i++) {
                float4 v = pr[i];
                sv[4*i+0] = v.x; sv[4*i+1] = v.y; sv[4*i+2] = v.z; sv[4*i+3] = v.w;
            }
            float mt = -1e30f;
            #pragma unroll
            for (int j = 0; j < 16; j++) mt = fmaxf(mt, sv[j]);
            mt = fmaxf(mt, __shfl_xor_sync(0xffffffffu, mt, 1));
            mt = fmaxf(mt, __shfl_xor_sync(0xffffffffu, mt, 2));
            float mold = rowM[sr];
            float mnew = fmaxf(mold, mt);
            float p[16];
            if (mnew < -1e29f) {
                #pragma unroll
                for (int j = 0; j < 16; j++) p[j] = 0.0f;
                if (sq == 0) rowC[sr] = 1.0f;
            } else {
                float corr = __expf(mold - mnew);
                float sum = 0.0f;
                #pragma unroll
                for (int j = 0; j < 16; j++) { p[j] = __expf(sv[j] - mnew); sum += p[j]; }
                sum += __shfl_xor_sync(0xffffffffu, sum, 1);
                sum += __shfl_xor_sync(0xffffffffu, sum, 2);
                if (sq == 0) {
                    rowM[sr] = mnew;
                    rowL[sr] = rowL[sr] * corr + sum;
                    rowC[sr] = corr;
                }
            }
            uint32_t* pw = Pbw + sr * PVLDW + sq * 8;
            #pragma unroll
            for (int j = 0; j < 8; j++) {
                float a = p[2*j], bq = p[2*j+1];
                float ha = __bfloat162float(__float2bfloat16(a));
                float hb = __bfloat162float(__float2bfloat16(bq));
                uint32_t hw = pack_bf2(a, bq);
                uint32_t lw = pack_bf2(a - ha, bq - hb);
                pw[j]      = hw;
                pw[32 + j] = hw;
                pw[64 + j] = lw;
            }
        }
        __syncthreads();

        // ---- rescale O, then P.V via mma over K'=192 (ldmatrix) ----
        {
            float cf0 = rowC[r0l + g], cf1 = rowC[r0l + g + 8];
            #pragma unroll
            for (int nt = 0; nt < 8; nt++) {
                O[nt][0] *= cf0; O[nt][1] *= cf0;
                O[nt][2] *= cf1; O[nt][3] *= cf1;
            }
        }
        #pragma unroll 4
        for (int kk = 0; kk < 12; kk++) {
            uint32_t af[4];
            ldsm4(af, aPaddr + kk * 32);
            #pragma unroll
            for (int p = 0; p < 4; p++) {
                uint32_t bv[4];
                ldsm4(bv, bVaddr + p * (16 * PVLDW << 2) + kk * 32);
                mma16816(O[p*2    ], af, &bv[0]);
                mma16816(O[p*2 + 1], af, &bv[2]);
            }
        }
    }

    __syncthreads();
    if (tid < 64) {
        float lsum = rowL[tid];
        rowC[tid] = 1.0f / lsum;
        g_lse[(size_t)bh * Ss + q0 + tid] = rowM[tid] + logf(lsum);
    }
    __syncthreads();
    {
        float invl0 = rowC[r0l + g], invl1 = rowC[r0l + g + 8];
        float* d0 = g_ctx + ((size_t)(b * Ss + q0 + r0l + g    )) * Dd + h * HDd;
        float* d1 = g_ctx + ((size_t)(b * Ss + q0 + r0l + g + 8)) * Dd + h * HDd;
        #pragma unroll
        for (int nt = 0; nt < 8; nt++) {
            int col = wo0 + nt * 8 + 2 * t;
            *(float2*)(d0 + col) = make_float2(O[nt][0] * invl0, O[nt][1] * invl0);
            *(float2*)(d1 + col) = make_float2(O[nt][2] * invl1, O[nt][3] * invl1);
        }
    }
}

// ---------------- avg_attn: stream spilled scores ----------------
__global__ __launch_bounds__(256)
void avg_kernel(float* __restrict__ avg)
{
    const int tid = threadIdx.x;
    const int b = blockIdx.z, qt = blockIdx.y, kt = blockIdx.x;
    const int q0 = qt * 64, k0 = kt * 64;
    const int r = tid >> 2, c0 = (tid & 3) * 16;
    float* drow = avg + ((size_t)(b * Ss + q0 + r)) * Ss + k0 + c0;

    if (kt > qt) {
        float4 z = make_float4(0.f, 0.f, 0.f, 0.f);
        #pragma unroll
        for (int i = 0; i < 4; i++) ((float4*)drow)[i] = z;
        return;
    }

    size_t tbase = ((size_t)b * NTRI + (size_t)(qt*(qt+1)/2 + kt)) * Hh * 4096;
    float acc[16];
    #pragma unroll
    for (int j = 0; j < 16; j++) acc[j] = 0.0f;

    for (int h = 0; h < Hh; h++) {
        float lse = g_lse[((size_t)(b * Hh + h)) * Ss + q0 + r];
        const float4* sp = (const float4*)(g_sc + tbase + (size_t)h * 4096 + r * 64 + c0);
        #pragma unroll
        for (int i = 0; i < 4; i++) {
            float4 s4 = sp[i];
            acc[4*i+0] += __expf(s4.x - lse);
            acc[4*i+1] += __expf(s4.y - lse);
            acc[4*i+2] += __expf(s4.z - lse);
            acc[4*i+3] += __expf(s4.w - lse);
        }
    }
    #pragma unroll
    for (int i = 0; i < 4; i++) {
        float4 v = make_float4(acc[4*i+0]*0.0625f, acc[4*i+1]*0.0625f,
                               acc[4*i+2]*0.0625f, acc[4*i+3]*0.0625f);
        ((float4*)drow)[i] = v;
    }
}

// ---------------- launch ----------------
extern "C" void kernel_launch(void* const* d_in, const int* in_sizes, int n_in,
                              void* d_out, int out_size)
{
    const float* x    = (const float*)d_in[0];
    const void*  kpm  = d_in[1];
    const float* inw  = (const float*)d_in[3];
    const float* inb  = (const float*)d_in[4];
    const float* outw = (const float*)d_in[5];
    const float* outb = (const float*)d_in[6];

    float* out = (float*)d_out;
    float* avg = out + OUT_ELEMS;

    cudaFuncSetAttribute(flash_kernel, cudaFuncAttributeMaxDynamicSharedMemorySize, FLASH_SMEM);
    cudaFuncSetAttribute(vsplit_kernel, cudaFuncAttributeMaxDynamicSharedMemorySize, VS_SMEM);

    mask_norm_kernel<<<1, 256>>>(kpm, BSr);

    {
        long long n4;
        n4 = (long long)BSr * Dd / 4;
        split_kernel<<<(unsigned)((n4 + 255) / 256), 256>>>(x, Dd, n4, 0, 0);
        n4 = (long long)3 * Dd * Dd / 4;
        split_kernel<<<(unsigned)((n4 + 255) / 256), 256>>>(inw, Dd, n4, 1, 1);
        n4 = (long long)Dd * Dd / 4;
        split_kernel<<<(unsigned)((n4 + 255) / 256), 256>>>(outw, Dd, n4, 1, 2);
    }

    // QKV projection (q/k split + v fp32)
    gemm_mma_kernel<<<dim3(3*Dd/128, BSr/128), 256>>>(0, inb, nullptr, 3*Dd, K3d, 1);

    // one-shot V transpose+split
    vsplit_kernel<<<dim3(Ss/128, Bb*Hh), 256, VS_SMEM>>>();

    // flash attention (spills scores, writes g_ctx fp32)
    flash_kernel<<<dim3(Ss/64, Bb*Hh), 256, FLASH_SMEM>>>();

    // avg_attn: stream scores
    avg_kernel<<<dim3(NT, NT, Bb), 256>>>(avg);

    // ctx split + output projection
    {
        long long n4 = (long long)BSr * Dd / 4;
        split_kernel<<<(unsigned)((n4 + 255) / 256), 256>>>(nullptr, Dd, n4, 0, 3);
    }
    gemm_mma_kernel<<<dim3(Dd/128, BSr/128), 256>>>(1, outb, out, Dd, K3d, 0);
}

// round 15
// speedup vs baseline: 1.2843x; 1.0254x over previous
#include <cuda_runtime.h>
#include <cuda_bf16.h>
#include <math.h>
#include <stdint.h>

#define Bb 2
#define Ss 2048
#define Dd 2048
#define Hh 16
#define HDd 128
#define BSr (Bb*Ss)
#define K3d (3*Dd)
#define KQ3 (3*HDd)                 // 384
#define NT 32
#define NTRI 528
#define OUT_ELEMS (Bb*Ss*Dd)
#define QSCALE 0.08838834764831843f

// ---------------- scratch (device globals; referenced only from device code) ----
__device__ float g_v[Bb*Hh*Ss*HDd];
__device__ float g_ctx[Bb*Ss*Dd];
__device__ float g_lse[Bb*Hh*Ss];
__device__ float g_kpm_add[BSr];
__device__ float g_sc[(size_t)Bb*NTRI*Hh*4096];       // biased scores, lower-tri tiles
__device__ __nv_bfloat16 g_qs[(size_t)Bb*Hh*Ss*KQ3];  // q split [h|h|l], pre-scaled
__device__ __nv_bfloat16 g_ks[(size_t)Bb*Hh*Ss*KQ3];  // k split [h|l|h]
__device__ __nv_bfloat16 g_vt[(size_t)Bb*Hh*HDd*3*Ss];// V^T split [bh][d][h|l|h over s]
__device__ __nv_bfloat16 g_xa[(size_t)BSr*K3d];
__device__ __nv_bfloat16 g_wia[(size_t)3*Dd*K3d];
__device__ __nv_bfloat16 g_woa[(size_t)Dd*K3d];
__device__ __nv_bfloat16 g_ctxa[(size_t)BSr*K3d];

__device__ __forceinline__ void mma16816(float* c, const uint32_t* a, const uint32_t* b) {
    asm volatile("mma.sync.aligned.m16n8k16.row.col.f32.bf16.bf16.f32 "
        "{%0,%1,%2,%3}, {%4,%5,%6,%7}, {%8,%9}, {%0,%1,%2,%3};"
        : "+f"(c[0]), "+f"(c[1]), "+f"(c[2]), "+f"(c[3])
        : "r"(a[0]), "r"(a[1]), "r"(a[2]), "r"(a[3]), "r"(b[0]), "r"(b[1]));
}
__device__ __forceinline__ void ldsm4(uint32_t* r, uint32_t saddr) {
    asm volatile("ldmatrix.sync.aligned.m8n8.x4.shared.b16 {%0,%1,%2,%3}, [%4];"
        : "=r"(r[0]), "=r"(r[1]), "=r"(r[2]), "=r"(r[3]) : "r"(saddr));
}
__device__ __forceinline__ uint32_t pack_bf2(float x, float y) {
    __nv_bfloat162 p = __floats2bfloat162_rn(x, y);
    return *(uint32_t*)&p;
}
__device__ __forceinline__ uint32_t smem_u32(const void* p) {
    uint32_t a;
    asm("{ .reg .u64 t; cvta.to.shared.u64 t, %1; cvt.u32.u64 %0, t; }" : "=r"(a) : "l"(p));
    return a;
}

// ---------------- key_padding_mask normalizer ----------------
__global__ void mask_norm_kernel(const void* kpm, int n)
{
    __shared__ int s_mode;
    __shared__ int c_upper, c_lower, c_fbad;
    const unsigned char* bp = (const unsigned char*)kpm;
    const float* fp = (const float*)kpm;
    int tid = threadIdx.x;
    if (tid == 0) { c_upper = 0; c_lower = 0; c_fbad = 0; }
    __syncthreads();
    for (int i = tid; i < n; i += blockDim.x) {
        unsigned char v = bp[i];
        if (v) { if (i & 3) atomicAdd(&c_upper, 1); else atomicAdd(&c_lower, 1); }
    }
    for (int i = tid; i < n / 4; i += blockDim.x) {
        float v = fp[i];
        if (!(v == 0.0f || v == 1.0f)) atomicAdd(&c_fbad, 1);
    }
    __syncthreads();
    if (tid == 0) {
        if (c_upper == 0 && c_lower == 0) s_mode = 2;
        else if (c_fbad == 0) s_mode = 0;
        else if (c_upper == 0) s_mode = 1;
        else s_mode = 2;
    }
    __syncthreads();
    int mode = s_mode;
    for (int i = tid; i < n; i += blockDim.x) {
        bool keep;
        if (mode == 0)      keep = (fp[i] != 0.0f);
        else if (mode == 1) keep = (((const int*)kpm)[i] != 0);
        else                keep = (bp[i] != 0);
        g_kpm_add[i] = keep ? 0.0f : -1e30f;
    }
}

// ---------------- fp32 -> bf16 hi/lo split ----------------
__global__ void split_kernel(const float* __restrict__ src,
                             int K, long long n4, int pat, int dsel)
{
    long long i = (long long)blockIdx.x * blockDim.x + threadIdx.x;
    if (i >= n4) return;
    if (src == nullptr) src = g_ctx;
    __nv_bfloat16* dst = (dsel == 0) ? g_xa : (dsel == 1) ? g_wia
                       : (dsel == 2) ? g_woa : g_ctxa;
    long long e = i * 4;
    float4 v = *(const float4*)(src + e);
    long long r = e / K; int k = (int)(e - r * K);
    float f[4] = {v.x, v.y, v.z, v.w};
    __nv_bfloat16 h[4], l[4];
    #pragma unroll
    for (int j = 0; j < 4; j++) {
        h[j] = __float2bfloat16(f[j]);
        l[j] = __float2bfloat16(f[j] - __bfloat162float(h[j]));
    }
    __nv_bfloat16* drow = dst + r * (long long)(3 * K);
    uint32_t hp0 = ((uint32_t)__bfloat16_as_ushort(h[1]) << 16) | __bfloat16_as_ushort(h[0]);
    uint32_t hp1 = ((uint32_t)__bfloat16_as_ushort(h[3]) << 16) | __bfloat16_as_ushort(h[2]);
    uint32_t lp0 = ((uint32_t)__bfloat16_as_ushort(l[1]) << 16) | __bfloat16_as_ushort(l[0]);
    uint32_t lp1 = ((uint32_t)__bfloat16_as_ushort(l[3]) << 16) | __bfloat16_as_ushort(l[2]);
    uint2 hp = make_uint2(hp0, hp1), lp = make_uint2(lp0, lp1);
    *(uint2*)(drow + k)         = hp;
    *(uint2*)(drow + K + k)     = pat ? lp : hp;
    *(uint2*)(drow + 2*K + k)   = pat ? hp : lp;
}

// ---------------- bf16 mma.sync NT GEMM (2-stage smem, 1 sync/chunk, ldmatrix) ---
#define LDW 36
#define HSTG 4608                    // words per A-or-B half stage (128*36)
#define STGW (2*HSTG)                // words per stage (A+B)
#define GM_SMEM (2*STGW*4)           // 73728 bytes

__global__ __launch_bounds__(256)
void gemm_mma_kernel(int absel, const float* __restrict__ bias, float* __restrict__ Cout,
                     int N, int K3, int epi)
{
    extern __shared__ uint32_t gsm[];

    const __nv_bfloat16* A2 = (absel == 0) ? g_xa  : g_ctxa;
    const __nv_bfloat16* B2 = (absel == 0) ? g_wia : g_woa;

    const int tid = threadIdx.x;
    const int m0 = blockIdx.y * 128, n0 = blockIdx.x * 128;
    const int NCH = K3 / 64;
    const int wstride = K3 / 2;

    const uint32_t* agw = (const uint32_t*)(A2 + (size_t)m0 * K3);
    const uint32_t* bgw = (const uint32_t*)(B2 + (size_t)n0 * K3);

    const int lrow0 = tid >> 3;
    const int lw    = (tid & 7) * 4;
    const int w = tid >> 5, l = tid & 31;
    const int wm = (w >> 2) * 64, wn = (w & 3) * 32;
    const int g = l >> 2, t = l & 3;

    // ldmatrix lane base addresses (stage 0, bytes); stage 1 = +STGW*4
    const uint32_t aAddr0 = smem_u32(gsm) + ((((wm + (l & 15)) * LDW) + ((l >> 4) << 2)) << 2);
    const uint32_t bAddr0 = smem_u32(gsm) + ((HSTG + ((wn + ((l >> 4) << 3) + (l & 7)) * LDW) + (((l >> 3) & 1) << 2)) << 2);

    float acc[4][4][4];
    #pragma unroll
    for (int i = 0; i < 4; i++)
        #pragma unroll
        for (int j = 0; j < 4; j++)
            #pragma unroll
            for (int q = 0; q < 4; q++) acc[i][j][q] = 0.0f;

    uint4 ra[4], rb[4];
    #pragma unroll
    for (int i = 0; i < 4; i++) {
        int row = lrow0 + i * 32;
        ra[i] = *(const uint4*)&agw[(size_t)row * wstride + lw];
        rb[i] = *(const uint4*)&bgw[(size_t)row * wstride + lw];
    }

    for (int c = 0; c < NCH; c++) {
        const int s = c & 1;
        uint32_t* Asw = gsm + s * STGW;
        uint32_t* Bsw = Asw + HSTG;
        // store staged chunk c into stage s (stage s last read at iter c-2, fenced by sync at c-1)
        #pragma unroll
        for (int i = 0; i < 4; i++) {
            int row = lrow0 + i * 32;
            *(uint4*)&Asw[row * LDW + lw] = ra[i];
            *(uint4*)&Bsw[row * LDW + lw] = rb[i];
        }
        __syncthreads();
        // stage chunk c+1 (loads overlap compute below)
        if (c + 1 < NCH) {
            const int cw = (c + 1) * 32;
            #pragma unroll
            for (int i = 0; i < 4; i++) {
                int row = lrow0 + i * 32;
                ra[i] = *(const uint4*)&agw[(size_t)row * wstride + cw + lw];
                rb[i] = *(const uint4*)&bgw[(size_t)row * wstride + cw + lw];
            }
        }
        const uint32_t soff = s * (STGW * 4);
        #pragma unroll
        for (int kk = 0; kk < 4; kk++) {
            uint32_t af[4][4];
            #pragma unroll
            for (int mt = 0; mt < 4; mt++)
                ldsm4(af[mt], aAddr0 + soff + mt * (16 * LDW * 4) + kk * 32);
            uint32_t b01[4], b23[4];
            ldsm4(b01, bAddr0 + soff + kk * 32);
            ldsm4(b23, bAddr0 + soff + 16 * LDW * 4 + kk * 32);
            #pragma unroll
            for (int mt = 0; mt < 4; mt++) {
                mma16816(acc[mt][0], af[mt], &b01[0]);
                mma16816(acc[mt][1], af[mt], &b01[2]);
                mma16816(acc[mt][2], af[mt], &b23[0]);
                mma16816(acc[mt][3], af[mt], &b23[2]);
            }
        }
        // no trailing sync: next store goes to the other stage
    }

    if (epi == 0) {
        float* dstbase = Cout + (size_t)m0 * N + n0;
        #pragma unroll
        for (int mt = 0; mt < 4; mt++)
            #pragma unroll
            for (int rr = 0; rr < 2; rr++) {
                int lr = wm + mt * 16 + g + rr * 8;
                float* drow = dstbase + (size_t)lr * N;
                #pragma unroll
                for (int nt = 0; nt < 4; nt++) {
                    int lc = wn + nt * 8 + 2 * t;
                    int gc = n0 + lc;
                    float2 v;
                    v.x = acc[mt][nt][rr*2 + 0] + bias[gc + 0];
                    v.y = acc[mt][nt][rr*2 + 1] + bias[gc + 1];
                    *(float2*)(drow + lc) = v;
                }
            }
    } else {
        int part = n0 >> 11, d2 = n0 & 2047;
        int h = d2 >> 7;
        int bb = m0 >> 11, s0 = m0 & 2047;
        if (part == 2) {
            float* dstbase = g_v + (((size_t)(bb * Hh + h)) * Ss + s0) * HDd;
            #pragma unroll
            for (int mt = 0; mt < 4; mt++)
                #pragma unroll
                for (int rr = 0; rr < 2; rr++) {
                    int lr = wm + mt * 16 + g + rr * 8;
                    float* drow = dstbase + (size_t)lr * HDd;
                    #pragma unroll
                    for (int nt = 0; nt < 4; nt++) {
                        int lc = wn + nt * 8 + 2 * t;
                        int gc = n0 + lc;
                        float2 v;
                        v.x = acc[mt][nt][rr*2 + 0] + bias[gc + 0];
                        v.y = acc[mt][nt][rr*2 + 1] + bias[gc + 1];
                        *(float2*)(drow + lc) = v;
                    }
                }
        } else {
            __nv_bfloat16* basep = (part == 0) ? g_qs : g_ks;
            float scale = (part == 0) ? QSCALE : 1.0f;
            __nv_bfloat16* dstbase = basep + (((size_t)(bb * Hh + h)) * Ss + s0) * (size_t)KQ3;
            #pragma unroll
            for (int mt = 0; mt < 4; mt++)
                #pragma unroll
                for (int rr = 0; rr < 2; rr++) {
                    int lr = wm + mt * 16 + g + rr * 8;
                    uint32_t* drow = (uint32_t*)(dstbase + (size_t)lr * KQ3);
                    #pragma unroll
                    for (int nt = 0; nt < 4; nt++) {
                        int lc = wn + nt * 8 + 2 * t;
                        int gc = n0 + lc;
                        float vx = (acc[mt][nt][rr*2 + 0] + bias[gc + 0]) * scale;
                        float vy = (acc[mt][nt][rr*2 + 1] + bias[gc + 1]) * scale;
                        float hx = __bfloat162float(__float2bfloat16(vx));
                        float hy = __bfloat162float(__float2bfloat16(vy));
                        uint32_t hi2 = pack_bf2(hx, hy);
                        uint32_t lo2 = pack_bf2(vx - hx, vy - hy);
                        int wd = lc >> 1;
                        drow[wd]       = hi2;
                        drow[64 + wd]  = (part == 0) ? hi2 : lo2;
                        drow[128 + wd] = (part == 0) ? lo2 : hi2;
                    }
                }
        }
    }
}

// ---------------- vsplit: g_v -> g_vt (transpose + hi/lo split, once) ----------
#define VS_SMEM (128*132*4)
__global__ __launch_bounds__(256)
void vsplit_kernel()
{
    extern __shared__ float vsm[];   // [128][132]
    const int tid = threadIdx.x;
    const int sch = blockIdx.x;
    const int bh = blockIdx.y;
    const int s0 = sch * 128;

    const float4* src = (const float4*)(g_v + ((size_t)bh * Ss + s0) * HDd);
    for (int idx = tid; idx < 128 * 32; idx += 256) {
        int row = idx >> 5, c4 = idx & 31;
        *(float4*)&vsm[row * 132 + c4 * 4] = src[row * 32 + c4];
    }
    __syncthreads();

    const int d = tid & 127, half = tid >> 7;
    uint32_t* dstb = (uint32_t*)g_vt + ((size_t)(bh * HDd + d) * 3) * (Ss/2) + ((s0 + half * 64) >> 1);
    #pragma unroll
    for (int g8 = 0; g8 < 8; g8++) {
        int sb = half * 64 + g8 * 8;
        float f[8];
        #pragma unroll
        for (int e = 0; e < 8; e++) f[e] = vsm[(sb + e) * 132 + d];
        uint32_t hw[4], lw[4];
        #pragma unroll
        for (int p = 0; p < 4; p++) {
            float a = f[2*p], bq = f[2*p+1];
            float ha = __bfloat162float(__float2bfloat16(a));
            float hb = __bfloat162float(__float2bfloat16(bq));
            hw[p] = pack_bf2(a, bq);
            lw[p] = pack_bf2(a - ha, bq - hb);
        }
        uint4 hv = make_uint4(hw[0], hw[1], hw[2], hw[3]);
        uint4 lv = make_uint4(lw[0], lw[1], lw[2], lw[3]);
        *(uint4*)&dstb[g8 * 4]              = hv;
        *(uint4*)&dstb[(Ss/2) + g8 * 4]     = lv;
        *(uint4*)&dstb[2*(Ss/2) + g8 * 4]   = hv;
    }
}

// ---------------- flash forward: ctx + lse + score spill (ldmatrix) -------------
#define QKLDW 196
#define PVLDW 100
#define FL_QS   0
#define FL_KS   (FL_QS + 64*QKLDW)
#define FL_VT   (FL_KS + 64*QKLDW)
#define FL_PB   (FL_VT + 128*PVLDW)
#define FL_PS   (FL_PB + 64*PVLDW)
#define FL_RM   (FL_PS + 64*68)
#define FL_RL   (FL_RM + 64)
#define FL_RC   (FL_RL + 64)
#define FL_KA   (FL_RC + 64)
#define FL_WORDS (FL_KA + 64)
#define FLASH_SMEM (FL_WORDS*4)

__global__ __launch_bounds__(256, 1)
void flash_kernel()
{
    extern __shared__ uint32_t smw[];
    uint32_t* Qw  = smw + FL_QS;
    uint32_t* Kw  = smw + FL_KS;
    uint32_t* Vtw = smw + FL_VT;
    uint32_t* Pbw = smw + FL_PB;
    float* Ps   = (float*)(smw + FL_PS);
    float* rowM = (float*)(smw + FL_RM);
    float* rowL = (float*)(smw + FL_RL);
    float* rowC = (float*)(smw + FL_RC);
    float* kadd = (float*)(smw + FL_KA);

    const int tid = threadIdx.x;
    const int bh = blockIdx.y;
    const int b = bh >> 4, h = bh & 15;
    const int qt = (int)gridDim.x - 1 - (int)blockIdx.x;
    const int q0 = qt * 64;
    const float slope = exp2f(-0.5f * (float)(h + 1));

    const int w = tid >> 5, l = tid & 31;
    const int wqk = w >> 1;
    const int wn0 = (w & 1) * 32;
    const int wo0 = (w & 1) * 64;
    const int g = l >> 2, t = l & 3;
    const int r0l = 16 * wqk;
    const int sr = tid >> 2, sq = tid & 3;

    const uint32_t aQaddr = smem_u32(Qw)  + ((((r0l + (l & 15)) * QKLDW) + ((l >> 4) << 2)) << 2);
    const uint32_t bKaddr = smem_u32(Kw)  + ((((wn0 + ((l >> 4) << 3) + (l & 7)) * QKLDW) + (((l >> 3) & 1) << 2)) << 2);
    const uint32_t aPaddr = smem_u32(Pbw) + ((((r0l + (l & 15)) * PVLDW) + ((l >> 4) << 2)) << 2);
    const uint32_t bVaddr = smem_u32(Vtw) + ((((wo0 + ((l >> 4) << 3) + (l & 7)) * PVLDW) + (((l >> 3) & 1) << 2)) << 2);

    {
        const int r = tid >> 2, u = tid & 3;
        const uint4* src = (const uint4*)(g_qs + ((size_t)bh * Ss + q0 + r) * KQ3);
        #pragma unroll
        for (int i = 0; i < 12; i++)
            *(uint4*)&Qw[r * QKLDW + (u + 4*i) * 4] = src[u + 4*i];
    }
    if (tid < 64) { rowM[tid] = -1e30f; rowL[tid] = 0.0f; }

    float O[8][4];
    #pragma unroll
    for (int i = 0; i < 8; i++)
        #pragma unroll
        for (int q = 0; q < 4; q++) O[i][q] = 0.0f;

    for (int kt = 0; kt <= qt; kt++) {
        const int k0 = kt * 64;
        float* scp = g_sc + (((size_t)b * NTRI + (size_t)(qt*(qt+1)/2 + kt)) * Hh + h) * 4096;
        __syncthreads();
        {
            const int r = tid >> 2, u = tid & 3;
            const uint4* src = (const uint4*)(g_ks + ((size_t)bh * Ss + k0 + r) * KQ3);
            #pragma unroll
            for (int i = 0; i < 12; i++)
                *(uint4*)&Kw[r * QKLDW + (u + 4*i) * 4] = src[u + 4*i];
        }
        {
            const int r2 = tid >> 1, u2 = tid & 1;
            const uint32_t* vtb = (const uint32_t*)g_vt + ((size_t)(bh * HDd + r2) * 3) * (Ss/2) + (k0 >> 1);
            #pragma unroll
            for (int i = 0; i < 12; i++) {
                int wpos = (u2 + 2*i) * 4;
                int seg = wpos >> 5, wseg = wpos & 31;
                *(uint4*)&Vtw[r2 * PVLDW + wpos] = *(const uint4*)(vtb + (size_t)seg * (Ss/2) + wseg);
            }
        }
        if (tid < 64) kadd[tid] = g_kpm_add[b * Ss + k0 + tid];
        __syncthreads();

        float sacc[4][4];
        #pragma unroll
        for (int i = 0; i < 4; i++)
            #pragma unroll
            for (int q = 0; q < 4; q++) sacc[i][q] = 0.0f;
        #pragma unroll 8
        for (int kk = 0; kk < 24; kk++) {
            uint32_t af[4], b01[4], b23[4];
            ldsm4(af, aQaddr + kk * 32);
            ldsm4(b01, bKaddr + kk * 32);
            ldsm4(b23, bKaddr + (16 * QKLDW << 2) + kk * 32);
            mma16816(sacc[0], af, &b01[0]);
            mma16816(sacc[1], af, &b01[2]);
            mma16816(sacc[2], af, &b23[0]);
            mma16816(sacc[3], af, &b23[2]);
        }
        #pragma unroll
        for (int nt = 0; nt < 4; nt++) {
            int colb = wn0 + nt * 8 + 2 * t;
            int kj0 = k0 + colb;
            float ka0 = kadd[colb], ka1 = kadd[colb + 1];
            int qi0 = q0 + r0l + g;
            int qi1 = qi0 + 8;
            float2 s0, s1;
            s0.x = (kj0     > qi0) ? -1e30f : sacc[nt][0] + (float)(kj0     - qi0) * slope + ka0;
            s0.y = (kj0 + 1 > qi0) ? -1e30f : sacc[nt][1] + (float)(kj0 + 1 - qi0) * slope + ka1;
            s1.x = (kj0     > qi1) ? -1e30f : sacc[nt][2] + (float)(kj0     - qi1) * slope + ka0;
            s1.y = (kj0 + 1 > qi1) ? -1e30f : sacc[nt][3] + (float)(kj0 + 1 - qi1) * slope + ka1;
            *(float2*)&Ps[(r0l + g    ) * 68 + colb] = s0;
            *(float2*)&Ps[(r0l + g + 8) * 68 + colb] = s1;
            *(float2*)&scp[(r0l + g    ) * 64 + colb] = s0;
            *(float2*)&scp[(r0l + g + 8) * 64 + colb] = s1;
        }
        __syncthreads();

        {
            float sv[16];
            const float4* pr = (const float4*)(Ps + sr * 68 + sq * 16);
            #pragma unroll
            for (int i = 0; i < 4; i++) {
                float4 v = pr[i];
                sv[4*i+0] = v.x; sv[4*i+1] = v.y; sv[4*i+2] = v.z; sv[4*i+3] = v.w;
            }
            float mt = -1e30f;
            #pragma unroll
            for (int j = 0; j < 16; j++) mt = fmaxf(mt, sv[j]);
            mt = fmaxf(mt, __shfl_xor_sync(0xffffffffu, mt, 1));
            mt = fmaxf(mt, __shfl_xor_sync(0xffffffffu, mt, 2));
            float mold = rowM[sr];
            float mnew = fmaxf(mold, mt);
            float p[16];
            if (mnew < -1e29f) {
                #pragma unroll
                for (int j = 0; j < 16; j++) p[j] = 0.0f;
                if (sq == 0) rowC[sr] = 1.0f;
            } else {
                float corr = __expf(mold - mnew);
                float sum = 0.0f;
                #pragma unroll
                for (int j = 0; j < 16; j++) { p[j] = __expf(sv[j] - mnew); sum += p[j]; }
                sum += __shfl_xor_sync(0xffffffffu, sum, 1);
                sum += __shfl_xor_sync(0xffffffffu, sum, 2);
                if (sq == 0) {
                    rowM[sr] = mnew;
                    rowL[sr] = rowL[sr] * corr + sum;
                    rowC[sr] = corr;
                }
            }
            uint32_t* pw = Pbw + sr * PVLDW + sq * 8;
            #pragma unroll
            for (int j = 0; j < 8; j++) {
                float a = p[2*j], bq = p[2*j+1];
                float ha = __bfloat162float(__float2bfloat16(a));
                float hb = __bfloat162float(__float2bfloat16(bq));
                uint32_t hw = pack_bf2(a, bq);
                uint32_t lw = pack_bf2(a - ha, bq - hb);
                pw[j]      = hw;
                pw[32 + j] = hw;
                pw[64 + j] = lw;
            }
        }
        __syncthreads();

        {
            float cf0 = rowC[r0l + g], cf1 = rowC[r0l + g + 8];
            #pragma unroll
            for (int nt = 0; nt < 8; nt++) {
                O[nt][0] *= cf0; O[nt][1] *= cf0;
                O[nt][2] *= cf1; O[nt][3] *= cf1;
            }
        }
        #pragma unroll 4
        for (int kk = 0; kk < 12; kk++) {
            uint32_t af[4];
            ldsm4(af, aPaddr + kk * 32);
            #pragma unroll
            for (int p = 0; p < 4; p++) {
                uint32_t bv[4];
                ldsm4(bv, bVaddr + p * (16 * PVLDW << 2) + kk * 32);
                mma16816(O[p*2    ], af, &bv[0]);
                mma16816(O[p*2 + 1], af, &bv[2]);
            }
        }
    }

    __syncthreads();
    if (tid < 64) {
        float lsum = rowL[tid];
        rowC[tid] = 1.0f / lsum;
        g_lse[(size_t)bh * Ss + q0 + tid] = rowM[tid] + logf(lsum);
    }
    __syncthreads();
    {
        float invl0 = rowC[r0l + g], invl1 = rowC[r0l + g + 8];
        float* d0 = g_ctx + ((size_t)(b * Ss + q0 + r0l + g    )) * Dd + h * HDd;
        float* d1 = g_ctx + ((size_t)(b * Ss + q0 + r0l + g + 8)) * Dd + h * HDd;
        #pragma unroll
        for (int nt = 0; nt < 8; nt++) {
            int col = wo0 + nt * 8 + 2 * t;
            *(float2*)(d0 + col) = make_float2(O[nt][0] * invl0, O[nt][1] * invl0);
            *(float2*)(d1 + col) = make_float2(O[nt][2] * invl1, O[nt][3] * invl1);
        }
    }
}

// ---------------- avg_attn: stream spilled scores ----------------
__global__ __launch_bounds__(256)
void avg_kernel(float* __restrict__ avg)
{
    const int tid = threadIdx.x;
    const int b = blockIdx.z, qt = blockIdx.y, kt = blockIdx.x;
    const int q0 = qt * 64, k0 = kt * 64;
    const int r = tid >> 2, c0 = (tid & 3) * 16;
    float* drow = avg + ((size_t)(b * Ss + q0 + r)) * Ss + k0 + c0;

    if (kt > qt) {
        float4 z = make_float4(0.f, 0.f, 0.f, 0.f);
        #pragma unroll
        for (int i = 0; i < 4; i++) ((float4*)drow)[i] = z;
        return;
    }

    size_t tbase = ((size_t)b * NTRI + (size_t)(qt*(qt+1)/2 + kt)) * Hh * 4096;
    float acc[16];
    #pragma unroll
    for (int j = 0; j < 16; j++) acc[j] = 0.0f;

    for (int h = 0; h < Hh; h++) {
        float lse = g_lse[((size_t)(b * Hh + h)) * Ss + q0 + r];
        const float4* sp = (const float4*)(g_sc + tbase + (size_t)h * 4096 + r * 64 + c0);
        #pragma unroll
        for (int i = 0; i < 4; i++) {
            float4 s4 = sp[i];
            acc[4*i+0] += __expf(s4.x - lse);
            acc[4*i+1] += __expf(s4.y - lse);
            acc[4*i+2] += __expf(s4.z - lse);
            acc[4*i+3] += __expf(s4.w - lse);
        }
    }
    #pragma unroll
    for (int i = 0; i < 4; i++) {
        float4 v = make_float4(acc[4*i+0]*0.0625f, acc[4*i+1]*0.0625f,
                               acc[4*i+2]*0.0625f, acc[4*i+3]*0.0625f);
        ((float4*)drow)[i] = v;
    }
}

// ---------------- launch ----------------
extern "C" void kernel_launch(void* const* d_in, const int* in_sizes, int n_in,
                              void* d_out, int out_size)
{
    const float* x    = (const float*)d_in[0];
    const void*  kpm  = d_in[1];
    const float* inw  = (const float*)d_in[3];
    const float* inb  = (const float*)d_in[4];
    const float* outw = (const float*)d_in[5];
    const float* outb = (const float*)d_in[6];

    float* out = (float*)d_out;
    float* avg = out + OUT_ELEMS;

    cudaFuncSetAttribute(gemm_mma_kernel, cudaFuncAttributeMaxDynamicSharedMemorySize, GM_SMEM);
    cudaFuncSetAttribute(flash_kernel, cudaFuncAttributeMaxDynamicSharedMemorySize, FLASH_SMEM);
    cudaFuncSetAttribute(vsplit_kernel, cudaFuncAttributeMaxDynamicSharedMemorySize, VS_SMEM);

    mask_norm_kernel<<<1, 256>>>(kpm, BSr);

    {
        long long n4;
        n4 = (long long)BSr * Dd / 4;
        split_kernel<<<(unsigned)((n4 + 255) / 256), 256>>>(x, Dd, n4, 0, 0);
        n4 = (long long)3 * Dd * Dd / 4;
        split_kernel<<<(unsigned)((n4 + 255) / 256), 256>>>(inw, Dd, n4, 1, 1);
        n4 = (long long)Dd * Dd / 4;
        split_kernel<<<(unsigned)((n4 + 255) / 256), 256>>>(outw, Dd, n4, 1, 2);
    }

    // QKV projection (q/k split + v fp32)
    gemm_mma_kernel<<<dim3(3*Dd/128, BSr/128), 256, GM_SMEM>>>(0, inb, nullptr, 3*Dd, K3d, 1);

    // one-shot V transpose+split
    vsplit_kernel<<<dim3(Ss/128, Bb*Hh), 256, VS_SMEM>>>();

    // flash attention (spills scores, writes g_ctx fp32)
    flash_kernel<<<dim3(Ss/64, Bb*Hh), 256, FLASH_SMEM>>>();

    // ---- fork: avg (stream s2) || ctx-split + out-proj (stream 0) ----
    cudaStream_t s2;
    cudaStreamCreateWithFlags(&s2, cudaStreamNonBlocking);
    cudaEvent_t e1, e2;
    cudaEventCreateWithFlags(&e1, cudaEventDisableTiming);
    cudaEventCreateWithFlags(&e2, cudaEventDisableTiming);

    cudaEventRecord(e1, 0);
    cudaStreamWaitEvent(s2, e1, 0);
    avg_kernel<<<dim3(NT, NT, Bb), 256, 0, s2>>>(avg);
    cudaEventRecord(e2, s2);

    {
        long long n4 = (long long)BSr * Dd / 4;
        split_kernel<<<(unsigned)((n4 + 255) / 256), 256>>>(nullptr, Dd, n4, 0, 3);
    }
    gemm_mma_kernel<<<dim3(Dd/128, BSr/128), 256, GM_SMEM>>>(1, outb, out, Dd, K3d, 0);

    cudaStreamWaitEvent(0, e2, 0);
    // NOTE: s2/e1/e2 intentionally not destroyed — destroying a stream that
    // participates in an in-progress capture invalidates the capture, and
    // kernel_launch is only invoked a handful of times (replays run the graph).
}